// round 8
// baseline (speedup 1.0000x reference)
#include <cuda_runtime.h>
#include <cuda_bf16.h>
#include <cstdint>

// Problem constants
#define BB   2
#define NB   32
#define PP   128
#define FF   32
#define HH   32
#define NODE_OUT 8
#define OUTD 32
#define BINS (BB*NB)            // 64
#define ROWS (BINS*PP)          // 8192
#define TI   8                  // i-rows per pair block

// Scratch (no cudaMalloc allowed)
__device__ float g_pa_buf[ROWS*OUTD];
__device__ float g_pb_buf[ROWS*OUTD];

__device__ __forceinline__ float eluf(float x) {
    float e = __expf(x) - 1.0f;
    return x > 0.0f ? x : e;
}

// ---------- Kernel A: node MLP + pa/pb projections (flat, scalar) ----------
__global__ void __launch_bounds__(128)
node_kernel(const float* __restrict__ x,
            const float* __restrict__ msk,
            const float* __restrict__ w0, const float* __restrict__ b0,
            const float* __restrict__ w1, const float* __restrict__ b1,
            const float* __restrict__ w2, const float* __restrict__ b2,
            const float* __restrict__ pw0) {
    __shared__ __align__(16) float sW0[FF*HH];   // 1024
    __shared__ __align__(16) float sW1[HH*HH];   // 1024
    __shared__ __align__(16) float sB0[HH], sB1[HH];
    __shared__ __align__(16) float sW2[HH*NODE_OUT];   // 256
    __shared__ __align__(16) float sWa[NODE_OUT*HH];   // 256
    __shared__ __align__(16) float sWb[NODE_OUT*HH];   // 256
    __shared__ __align__(16) float sB2[NODE_OUT];

    int tid = threadIdx.x;
    for (int idx = tid; idx < 1024; idx += 128) { sW0[idx] = w0[idx]; sW1[idx] = w1[idx]; }
    for (int idx = tid; idx < 256; idx += 128) {
        sW2[idx] = w2[idx];
        sWa[idx] = pw0[idx];                       // rows 0..7 of pair_w0
        sWb[idx] = pw0[NODE_OUT*HH + idx];         // rows 8..15
    }
    if (tid < 32) { sB0[tid] = b0[tid]; sB1[tid] = b1[tid]; }
    if (tid < NODE_OUT) sB2[tid] = b2[tid];
    __syncthreads();

    int r = blockIdx.x * 128 + tid;

    float v[HH];
    {
        const float4* gx4 = reinterpret_cast<const float4*>(x + (size_t)r * FF);
        #pragma unroll
        for (int q = 0; q < 8; q++) {
            float4 t = gx4[q];
            v[4*q] = t.x; v[4*q+1] = t.y; v[4*q+2] = t.z; v[4*q+3] = t.w;
        }
    }

    float a[HH];

    // layer 0: v = elu(v @ W0 + b0)
    #pragma unroll
    for (int k = 0; k < HH; k++) a[k] = sB0[k];
    #pragma unroll
    for (int f = 0; f < FF; f++) {
        float vf = v[f];
        const float4* wr = reinterpret_cast<const float4*>(sW0 + f * HH);
        #pragma unroll
        for (int q = 0; q < 8; q++) {
            float4 w4 = wr[q];
            a[4*q]   = fmaf(vf, w4.x, a[4*q]);
            a[4*q+1] = fmaf(vf, w4.y, a[4*q+1]);
            a[4*q+2] = fmaf(vf, w4.z, a[4*q+2]);
            a[4*q+3] = fmaf(vf, w4.w, a[4*q+3]);
        }
    }
    #pragma unroll
    for (int k = 0; k < HH; k++) v[k] = eluf(a[k]);

    // layer 1: v = elu(v @ W1 + b1)
    #pragma unroll
    for (int k = 0; k < HH; k++) a[k] = sB1[k];
    #pragma unroll
    for (int f = 0; f < HH; f++) {
        float vf = v[f];
        const float4* wr = reinterpret_cast<const float4*>(sW1 + f * HH);
        #pragma unroll
        for (int q = 0; q < 8; q++) {
            float4 w4 = wr[q];
            a[4*q]   = fmaf(vf, w4.x, a[4*q]);
            a[4*q+1] = fmaf(vf, w4.y, a[4*q+1]);
            a[4*q+2] = fmaf(vf, w4.z, a[4*q+2]);
            a[4*q+3] = fmaf(vf, w4.w, a[4*q+3]);
        }
    }
    #pragma unroll
    for (int k = 0; k < HH; k++) v[k] = eluf(a[k]);

    // node_proj = elu(v @ W2 + b2) * msk
    float m = msk[r];
    float np[NODE_OUT];
    #pragma unroll
    for (int k = 0; k < NODE_OUT; k++) {
        float acc = sB2[k];
        #pragma unroll
        for (int f = 0; f < HH; f++) acc = fmaf(v[f], sW2[f*NODE_OUT + k], acc);
        np[k] = eluf(acc) * m;
    }

    // pa = np @ Wa, pb = np @ Wb
    float pa[HH], pb[HH];
    #pragma unroll
    for (int k = 0; k < HH; k++) { pa[k] = 0.f; pb[k] = 0.f; }
    #pragma unroll
    for (int c = 0; c < NODE_OUT; c++) {
        float nc = np[c];
        #pragma unroll
        for (int k = 0; k < HH; k++) {
            pa[k] = fmaf(nc, sWa[c*HH + k], pa[k]);
            pb[k] = fmaf(nc, sWb[c*HH + k], pb[k]);
        }
    }
    float4* gpa4 = reinterpret_cast<float4*>(g_pa_buf + (size_t)r * HH);
    float4* gpb4 = reinterpret_cast<float4*>(g_pb_buf + (size_t)r * HH);
    #pragma unroll
    for (int q = 0; q < 8; q++) {
        gpa4[q] = make_float4(pa[4*q], pa[4*q+1], pa[4*q+2], pa[4*q+3]);
        gpb4[q] = make_float4(pb[4*q], pb[4*q+1], pb[4*q+2], pb[4*q+3]);
    }
}

// ---------- Kernel B: pair stage (flat, scalar) ----------
// grid: (16 i-tiles, 64 bins), 128 threads; thread j owns pairs (i0..i0+7, j)
__global__ void __launch_bounds__(128)
pair_kernel(const float* __restrict__ pb0,
            const float* __restrict__ pw1, const float* __restrict__ pb1,
            const float* __restrict__ pw2, const float* __restrict__ pb2,
            float* __restrict__ out) {
    __shared__ __align__(16) float s_pb[PP * 36];      // padded stride 36 floats
    __shared__ __align__(16) float s_paib[TI * HH];
    __shared__ __align__(16) float sW1[HH*HH];         // 1024
    __shared__ __align__(16) float sW2[HH*OUTD];       // 1024
    __shared__ __align__(16) float sB1[HH], sB2[OUTD];

    int tid = threadIdx.x;
    int bin = blockIdx.y;
    int i0  = blockIdx.x * TI;

    // pb tile for this bin (128 x 32), padded rows
    {
        const float4* gpb4 = reinterpret_cast<const float4*>(g_pb_buf + (size_t)bin * PP * HH);
        float4* dst = reinterpret_cast<float4*>(s_pb + tid * 36);
        #pragma unroll
        for (int q = 0; q < 8; q++) dst[q] = gpb4[tid * 8 + q];
    }

    // pa rows for this i-tile, with pair_b0 pre-added
    for (int idx = tid; idx < TI * HH; idx += 128) {
        int ii = idx >> 5, f = idx & 31;
        s_paib[idx] = g_pa_buf[(size_t)(bin * PP + i0 + ii) * HH + f] + pb0[f];
    }

    for (int idx = tid; idx < 1024; idx += 128) { sW1[idx] = pw1[idx]; sW2[idx] = pw2[idx]; }
    if (tid < 32) { sB1[tid] = pb1[tid]; sB2[tid] = pb2[tid]; }
    __syncthreads();

    int j = tid;
    float4* outp = reinterpret_cast<float4*>(out)
                 + ((size_t)(bin * PP + i0) * PP + j) * (OUTD / 4);

    #pragma unroll 1
    for (int ii = 0; ii < TI; ii++) {
        float v[HH];
        {
            const float4* pbrow = reinterpret_cast<const float4*>(s_pb + j * 36);
            const float4* pib4  = reinterpret_cast<const float4*>(s_paib + ii * HH);
            #pragma unroll
            for (int q = 0; q < 8; q++) {
                float4 pv = pbrow[q];
                float4 pi = pib4[q];
                v[4*q]   = eluf(pi.x + pv.x);
                v[4*q+1] = eluf(pi.y + pv.y);
                v[4*q+2] = eluf(pi.z + pv.z);
                v[4*q+3] = eluf(pi.w + pv.w);
            }
        }

        float a[HH];

        // h2 = elu(v @ W1 + b1)
        #pragma unroll
        for (int k = 0; k < HH; k++) a[k] = sB1[k];
        #pragma unroll
        for (int f = 0; f < HH; f++) {
            float vf = v[f];
            const float4* wr = reinterpret_cast<const float4*>(sW1 + f * HH);
            #pragma unroll
            for (int q = 0; q < 8; q++) {
                float4 w4 = wr[q];
                a[4*q]   = fmaf(vf, w4.x, a[4*q]);
                a[4*q+1] = fmaf(vf, w4.y, a[4*q+1]);
                a[4*q+2] = fmaf(vf, w4.z, a[4*q+2]);
                a[4*q+3] = fmaf(vf, w4.w, a[4*q+3]);
            }
        }
        #pragma unroll
        for (int k = 0; k < HH; k++) v[k] = eluf(a[k]);

        // o = elu(v @ W2 + b2)
        #pragma unroll
        for (int k = 0; k < OUTD; k++) a[k] = sB2[k];
        #pragma unroll
        for (int f = 0; f < HH; f++) {
            float vf = v[f];
            const float4* wr = reinterpret_cast<const float4*>(sW2 + f * OUTD);
            #pragma unroll
            for (int q = 0; q < 8; q++) {
                float4 w4 = wr[q];
                a[4*q]   = fmaf(vf, w4.x, a[4*q]);
                a[4*q+1] = fmaf(vf, w4.y, a[4*q+1]);
                a[4*q+2] = fmaf(vf, w4.z, a[4*q+2]);
                a[4*q+3] = fmaf(vf, w4.w, a[4*q+3]);
            }
        }

        #pragma unroll
        for (int q = 0; q < 8; q++)
            outp[q] = make_float4(eluf(a[4*q]), eluf(a[4*q+1]),
                                  eluf(a[4*q+2]), eluf(a[4*q+3]));
        outp += (size_t)PP * (OUTD / 4);
    }
}

// ---------- launch ----------
extern "C" void kernel_launch(void* const* d_in, const int* in_sizes, int n_in,
                              void* d_out, int out_size) {
    const float* x    = (const float*)d_in[0];
    const float* msk  = (const float*)d_in[1];
    const float* nw0  = (const float*)d_in[2];
    const float* nb0  = (const float*)d_in[3];
    const float* nw1  = (const float*)d_in[4];
    const float* nb1  = (const float*)d_in[5];
    const float* nw2  = (const float*)d_in[6];
    const float* nb2  = (const float*)d_in[7];
    const float* pw0  = (const float*)d_in[8];
    const float* pb0  = (const float*)d_in[9];
    const float* pw1  = (const float*)d_in[10];
    const float* pb1  = (const float*)d_in[11];
    const float* pw2  = (const float*)d_in[12];
    const float* pb2  = (const float*)d_in[13];
    float* out = (float*)d_out;

    node_kernel<<<ROWS / 128, 128>>>(x, msk, nw0, nb0, nw1, nb1, nw2, nb2, pw0);
    pair_kernel<<<dim3(PP / TI, BINS), 128>>>(pb0, pw1, pb1, pw2, pb2, out);
}

// round 15
// speedup vs baseline: 8.8797x; 8.8797x over previous
#include <cuda_runtime.h>
#include <cuda_bf16.h>
#include <cstdint>

// Problem constants
#define BB   2
#define NB   32
#define PP   128
#define FF   32
#define HH   32
#define NODE_OUT 8
#define OUTD 32
#define BINS (BB*NB)            // 64
#define ROWS (BINS*PP)          // 8192
#define TI   8                  // i-rows per pair block
#define VS   33                 // padded per-thread smem stride (conflict-free)

// Scratch (no cudaMalloc allowed)
__device__ float g_pa_buf[ROWS*HH];
__device__ float g_pb_buf[ROWS*HH];

__device__ __forceinline__ float eluf(float x) {
    float e = __expf(x) - 1.0f;
    return x > 0.0f ? x : e;
}

// ---------- Kernel A: node MLP + pa/pb projections (R8 form, known-good) ----------
__global__ void __launch_bounds__(128)
node_kernel(const float* __restrict__ x,
            const float* __restrict__ msk,
            const float* __restrict__ w0, const float* __restrict__ b0,
            const float* __restrict__ w1, const float* __restrict__ b1,
            const float* __restrict__ w2, const float* __restrict__ b2,
            const float* __restrict__ pw0) {
    __shared__ __align__(16) float sW0[FF*HH];   // 1024
    __shared__ __align__(16) float sW1[HH*HH];   // 1024
    __shared__ __align__(16) float sB0[HH], sB1[HH];
    __shared__ __align__(16) float sW2[HH*NODE_OUT];   // 256
    __shared__ __align__(16) float sWa[NODE_OUT*HH];   // 256
    __shared__ __align__(16) float sWb[NODE_OUT*HH];   // 256
    __shared__ __align__(16) float sB2[NODE_OUT];

    int tid = threadIdx.x;
    for (int idx = tid; idx < 1024; idx += 128) { sW0[idx] = w0[idx]; sW1[idx] = w1[idx]; }
    for (int idx = tid; idx < 256; idx += 128) {
        sW2[idx] = w2[idx];
        sWa[idx] = pw0[idx];                       // rows 0..7 of pair_w0
        sWb[idx] = pw0[NODE_OUT*HH + idx];         // rows 8..15
    }
    if (tid < 32) { sB0[tid] = b0[tid]; sB1[tid] = b1[tid]; }
    if (tid < NODE_OUT) sB2[tid] = b2[tid];
    __syncthreads();

    int r = blockIdx.x * 128 + tid;

    float v[HH];
    {
        const float4* gx4 = reinterpret_cast<const float4*>(x + (size_t)r * FF);
        #pragma unroll
        for (int q = 0; q < 8; q++) {
            float4 t = gx4[q];
            v[4*q] = t.x; v[4*q+1] = t.y; v[4*q+2] = t.z; v[4*q+3] = t.w;
        }
    }

    float a[HH];

    // layer 0: v = elu(v @ W0 + b0)
    #pragma unroll
    for (int k = 0; k < HH; k++) a[k] = sB0[k];
    #pragma unroll
    for (int f = 0; f < FF; f++) {
        float vf = v[f];
        const float4* wr = reinterpret_cast<const float4*>(sW0 + f * HH);
        #pragma unroll
        for (int q = 0; q < 8; q++) {
            float4 w4 = wr[q];
            a[4*q]   = fmaf(vf, w4.x, a[4*q]);
            a[4*q+1] = fmaf(vf, w4.y, a[4*q+1]);
            a[4*q+2] = fmaf(vf, w4.z, a[4*q+2]);
            a[4*q+3] = fmaf(vf, w4.w, a[4*q+3]);
        }
    }
    #pragma unroll
    for (int k = 0; k < HH; k++) v[k] = eluf(a[k]);

    // layer 1: v = elu(v @ W1 + b1)
    #pragma unroll
    for (int k = 0; k < HH; k++) a[k] = sB1[k];
    #pragma unroll
    for (int f = 0; f < HH; f++) {
        float vf = v[f];
        const float4* wr = reinterpret_cast<const float4*>(sW1 + f * HH);
        #pragma unroll
        for (int q = 0; q < 8; q++) {
            float4 w4 = wr[q];
            a[4*q]   = fmaf(vf, w4.x, a[4*q]);
            a[4*q+1] = fmaf(vf, w4.y, a[4*q+1]);
            a[4*q+2] = fmaf(vf, w4.z, a[4*q+2]);
            a[4*q+3] = fmaf(vf, w4.w, a[4*q+3]);
        }
    }
    #pragma unroll
    for (int k = 0; k < HH; k++) v[k] = eluf(a[k]);

    // node_proj = elu(v @ W2 + b2) * msk
    float m = msk[r];
    float np[NODE_OUT];
    #pragma unroll
    for (int k = 0; k < NODE_OUT; k++) {
        float acc = sB2[k];
        #pragma unroll
        for (int f = 0; f < HH; f++) acc = fmaf(v[f], sW2[f*NODE_OUT + k], acc);
        np[k] = eluf(acc) * m;
    }

    // pa = np @ Wa, pb = np @ Wb
    float pa[HH], pb[HH];
    #pragma unroll
    for (int k = 0; k < HH; k++) { pa[k] = 0.f; pb[k] = 0.f; }
    #pragma unroll
    for (int c = 0; c < NODE_OUT; c++) {
        float nc = np[c];
        #pragma unroll
        for (int k = 0; k < HH; k++) {
            pa[k] = fmaf(nc, sWa[c*HH + k], pa[k]);
            pb[k] = fmaf(nc, sWb[c*HH + k], pb[k]);
        }
    }
    float4* gpa4 = reinterpret_cast<float4*>(g_pa_buf + (size_t)r * HH);
    float4* gpb4 = reinterpret_cast<float4*>(g_pb_buf + (size_t)r * HH);
    #pragma unroll
    for (int q = 0; q < 8; q++) {
        gpa4[q] = make_float4(pa[4*q], pa[4*q+1], pa[4*q+2], pa[4*q+3]);
        gpb4[q] = make_float4(pb[4*q], pb[4*q+1], pb[4*q+2], pb[4*q+3]);
    }
}

// ---------- Kernel B: pair stage (rolled f-loops, smem-staged vectors) ----------
// grid: (16 i-tiles, 64 bins), 128 threads; thread j owns pairs (i0..i0+7, j)
__global__ void __launch_bounds__(128, 4)
pair_kernel(const float* __restrict__ pb0,
            const float* __restrict__ pw1, const float* __restrict__ pb1,
            const float* __restrict__ pw2, const float* __restrict__ pb2,
            float* __restrict__ out) {
    __shared__ float s_pb[PP * VS];                 // pb tile, stride-33 scalar layout
    __shared__ float s_v[PP * VS];                  // per-thread layer-1 outputs
    __shared__ float s_paib[TI * HH];               // pa rows + pair_b0
    __shared__ __align__(16) float sW1[HH*HH];      // 1024
    __shared__ __align__(16) float sW2[HH*OUTD];    // 1024
    __shared__ float sB1[HH], sB2[OUTD];

    int tid = threadIdx.x;
    int bin = blockIdx.y;
    int i0  = blockIdx.x * TI;

    // pb tile (128 x 32) -> stride-33 scalar layout
    {
        const float4* g4 = reinterpret_cast<const float4*>(g_pb_buf + (size_t)bin * PP * HH);
        #pragma unroll
        for (int t = 0; t < 8; t++) {
            int idx = tid + t * 128;        // float4 index 0..1023
            float4 val = g4[idx];
            int row = idx >> 3;             // 8 float4 per row
            int c4  = (idx & 7) * 4;
            float* d = s_pb + row * VS + c4;
            d[0] = val.x; d[1] = val.y; d[2] = val.z; d[3] = val.w;
        }
    }

    // pa rows for this i-tile, with pair_b0 pre-added
    for (int idx = tid; idx < TI * HH; idx += 128) {
        int ii = idx >> 5, f = idx & 31;
        s_paib[idx] = g_pa_buf[(size_t)(bin * PP + i0 + ii) * HH + f] + pb0[f];
    }

    for (int idx = tid; idx < 1024; idx += 128) { sW1[idx] = pw1[idx]; sW2[idx] = pw2[idx]; }
    if (tid < 32) { sB1[tid] = pb1[tid]; sB2[tid] = pb2[tid]; }
    __syncthreads();

    const float* my_pb = s_pb + tid * VS;
    float*       my_v  = s_v  + tid * VS;
    float4* outp = reinterpret_cast<float4*>(out)
                 + ((size_t)(bin * PP + i0) * PP + tid) * (OUTD / 4);

    #pragma unroll 1
    for (int ii = 0; ii < TI; ii++) {
        const float* pai = s_paib + ii * HH;
        float acc[HH];

        // layer 1: acc = (elu(pa_i + pb_j + b0)) @ W1 + b1  -- f-loop ROLLED
        #pragma unroll
        for (int k = 0; k < HH; k++) acc[k] = sB1[k];
        #pragma unroll 1
        for (int f = 0; f < HH; f++) {
            float vf = eluf(pai[f] + my_pb[f]);
            const float4* wr = reinterpret_cast<const float4*>(sW1 + f * HH);
            #pragma unroll
            for (int q = 0; q < 8; q++) {
                float4 w4 = wr[q];
                acc[4*q]   = fmaf(vf, w4.x, acc[4*q]);
                acc[4*q+1] = fmaf(vf, w4.y, acc[4*q+1]);
                acc[4*q+2] = fmaf(vf, w4.z, acc[4*q+2]);
                acc[4*q+3] = fmaf(vf, w4.w, acc[4*q+3]);
            }
        }
        // stage elu(acc) into per-thread smem (layer-2 input)
        #pragma unroll
        for (int k = 0; k < HH; k++) my_v[k] = eluf(acc[k]);

        // layer 2: acc = h2 @ W2 + b2  -- f-loop ROLLED, input from smem
        #pragma unroll
        for (int k = 0; k < OUTD; k++) acc[k] = sB2[k];
        #pragma unroll 1
        for (int f = 0; f < HH; f++) {
            float vf = my_v[f];
            const float4* wr = reinterpret_cast<const float4*>(sW2 + f * OUTD);
            #pragma unroll
            for (int q = 0; q < 8; q++) {
                float4 w4 = wr[q];
                acc[4*q]   = fmaf(vf, w4.x, acc[4*q]);
                acc[4*q+1] = fmaf(vf, w4.y, acc[4*q+1]);
                acc[4*q+2] = fmaf(vf, w4.z, acc[4*q+2]);
                acc[4*q+3] = fmaf(vf, w4.w, acc[4*q+3]);
            }
        }

        #pragma unroll
        for (int q = 0; q < 8; q++)
            outp[q] = make_float4(eluf(acc[4*q]), eluf(acc[4*q+1]),
                                  eluf(acc[4*q+2]), eluf(acc[4*q+3]));
        outp += (size_t)PP * (OUTD / 4);
    }
}

// ---------- launch ----------
extern "C" void kernel_launch(void* const* d_in, const int* in_sizes, int n_in,
                              void* d_out, int out_size) {
    const float* x    = (const float*)d_in[0];
    const float* msk  = (const float*)d_in[1];
    const float* nw0  = (const float*)d_in[2];
    const float* nb0  = (const float*)d_in[3];
    const float* nw1  = (const float*)d_in[4];
    const float* nb1  = (const float*)d_in[5];
    const float* nw2  = (const float*)d_in[6];
    const float* nb2  = (const float*)d_in[7];
    const float* pw0  = (const float*)d_in[8];
    const float* pb0  = (const float*)d_in[9];
    const float* pw1  = (const float*)d_in[10];
    const float* pb1  = (const float*)d_in[11];
    const float* pw2  = (const float*)d_in[12];
    const float* pb2  = (const float*)d_in[13];
    float* out = (float*)d_out;

    node_kernel<<<ROWS / 128, 128>>>(x, msk, nw0, nb0, nw1, nb1, nw2, nb2, pw0);
    pair_kernel<<<dim3(PP / TI, BINS), 128>>>(pb0, pw1, pb1, pw2, pb2, out);
}